// round 1
// baseline (speedup 1.0000x reference)
#include <cuda_runtime.h>
#include <mma.h>

using namespace nvcuda;

#define NWIN 4096       // 4 * 32 * 32 windows
#define LTOK 64         // tokens per window (8x8)
#define CCH  192        // channels
#define NH   6
#define HD   32
#define NTHREADS 256

// smem strides (floats), padded to dodge the worst bank conflicts
#define XS_LD  200
#define QK_LD  104
#define AL_LD  72
#define OUT_LD 200

#define SMEM_FLOATS (64*XS_LD + 64*OUT_LD + 64*QK_LD + 64*AL_LD + 64*64)
#define SMEM_BYTES  (SMEM_FLOATS * 4)   // 163840 B

__device__ __forceinline__ void cvt_frag_a(
    wmma::fragment<wmma::matrix_a,16,16,8,wmma::precision::tf32,wmma::row_major>& f) {
#pragma unroll
    for (int i = 0; i < f.num_elements; i++) f.x[i] = wmma::__float_to_tf32(f.x[i]);
}
__device__ __forceinline__ void cvt_frag_b_col(
    wmma::fragment<wmma::matrix_b,16,16,8,wmma::precision::tf32,wmma::col_major>& f) {
#pragma unroll
    for (int i = 0; i < f.num_elements; i++) f.x[i] = wmma::__float_to_tf32(f.x[i]);
}
__device__ __forceinline__ void cvt_frag_b_row(
    wmma::fragment<wmma::matrix_b,16,16,8,wmma::precision::tf32,wmma::row_major>& f) {
#pragma unroll
    for (int i = 0; i < f.num_elements; i++) f.x[i] = wmma::__float_to_tf32(f.x[i]);
}

__global__ __launch_bounds__(NTHREADS, 1)
void win_attn_kernel(const float* __restrict__ x,
                     const float* __restrict__ qkv_w,
                     const float* __restrict__ qkv_b,
                     const float* __restrict__ proj_w,
                     const float* __restrict__ proj_b,
                     const float* __restrict__ bias,
                     float* __restrict__ out)
{
    extern __shared__ float smem[];
    float* xs    = smem;                     // [64][XS_LD]  x window (fp32)
    float* outs  = xs    + 64 * XS_LD;       // [64][OUT_LD] concat head outputs
    float* qkvs  = outs  + 64 * OUT_LD;      // [64][QK_LD]  q|k|v per head (32+32+32)
    float* als   = qkvs  + 64 * QK_LD;       // [64][AL_LD]  attention logits/probs
    float* sbias = als   + 64 * AL_LD;       // [64][64]     per-head rel pos bias

    const int tid = threadIdx.x;
    const int wid = tid >> 5;

    const int w   = blockIdx.x;
    const int b   = w >> 10;
    const int rem = w & 1023;
    const int wh  = rem >> 5;
    const int ww  = rem & 31;

    const float scale = 0.17677669529663687f; // 1/sqrt(32)

    // ---- load x window (64 x 192) into smem, coalesced float4 ----
    {
        const float* xb = x + (size_t)b * 65536 * CCH;
        for (int i = tid; i < 64 * 48; i += NTHREADS) {
            int r  = i / 48;
            int c4 = i % 48;
            int iy = wh * 8 + (r >> 3);
            int ix = ww * 8 + (r & 7);
            float4 v = *(const float4*)(xb + (size_t)(iy * 256 + ix) * CCH + c4 * 4);
            *(float4*)(xs + r * XS_LD + c4 * 4) = v;
        }
    }
    __syncthreads();

    // ================= per-head loop =================
    for (int h = 0; h < NH; ++h) {
        // ---- GEMM1: qkvs(64x96) = xs(64x192) @ Wh^T  (B loaded col-major from global) ----
        for (int t = wid; t < 24; t += 8) {
            int mt = t & 3;          // 0..3 row tiles
            int nt = t >> 2;         // 0..5 col tiles (q0,q1,k0,k1,v0,v1)
            wmma::fragment<wmma::accumulator,16,16,8,float> acc;
            wmma::fill_fragment(acc, 0.0f);
            int blk = nt >> 1;       // 0=q,1=k,2=v
            int base_row = blk * 192 + h * 32 + (nt & 1) * 16;
            const float* Bp = qkv_w + (size_t)base_row * CCH;
#pragma unroll 4
            for (int kt = 0; kt < 24; ++kt) {
                wmma::fragment<wmma::matrix_a,16,16,8,wmma::precision::tf32,wmma::row_major> af;
                wmma::fragment<wmma::matrix_b,16,16,8,wmma::precision::tf32,wmma::col_major> bf;
                wmma::load_matrix_sync(af, xs + mt * 16 * XS_LD + kt * 8, XS_LD);
                wmma::load_matrix_sync(bf, Bp + kt * 8, CCH);
                cvt_frag_a(af); cvt_frag_b_col(bf);
                wmma::mma_sync(acc, af, bf, acc);
            }
            wmma::store_matrix_sync(qkvs + mt * 16 * QK_LD + nt * 16, acc, QK_LD, wmma::mem_row_major);
        }
        __syncthreads();

        // ---- bias fixup (+ fold softmax scale into q) and stage per-head rel-pos bias ----
        for (int i = tid; i < 64 * 96; i += NTHREADS) {
            int r = i / 96, j = i % 96;
            int blk = j >> 5;
            float bv = qkv_b[blk * 192 + h * 32 + (j & 31)];
            float v = qkvs[r * QK_LD + j] + bv;
            if (blk == 0) v *= scale;
            qkvs[r * QK_LD + j] = v;
        }
        {
            const float4* bsrc = (const float4*)(bias + (size_t)h * 4096);
            float4* bdst = (float4*)sbias;
            for (int i = tid; i < 1024; i += NTHREADS) bdst[i] = bsrc[i];
        }
        __syncthreads();

        // ---- logits: als(64x64) = q_scaled(64x32) @ k^T ----
        for (int t = wid; t < 16; t += 8) {
            int mt = t & 3;
            int nt = t >> 2;
            wmma::fragment<wmma::accumulator,16,16,8,float> acc;
            wmma::fill_fragment(acc, 0.0f);
#pragma unroll
            for (int kt = 0; kt < 4; ++kt) {
                wmma::fragment<wmma::matrix_a,16,16,8,wmma::precision::tf32,wmma::row_major> af;
                wmma::fragment<wmma::matrix_b,16,16,8,wmma::precision::tf32,wmma::col_major> bf;
                wmma::load_matrix_sync(af, qkvs + mt * 16 * QK_LD + kt * 8, QK_LD);
                wmma::load_matrix_sync(bf, qkvs + nt * 16 * QK_LD + 32 + kt * 8, QK_LD);
                cvt_frag_a(af); cvt_frag_b_col(bf);
                wmma::mma_sync(acc, af, bf, acc);
            }
            wmma::store_matrix_sync(als + mt * 16 * AL_LD + nt * 16, acc, AL_LD, wmma::mem_row_major);
        }
        __syncthreads();

        // ---- softmax over rows (64 rows x 64 cols), 4 threads per row ----
        {
            int r  = tid >> 2;
            int l4 = tid & 3;
            float* row = als + r * AL_LD;
            const float* brow = sbias + r * 64;
            float vals[16];
            float mx = -1e30f;
#pragma unroll
            for (int i = 0; i < 16; ++i) {
                float v = row[l4 * 16 + i] + brow[l4 * 16 + i];
                vals[i] = v;
                mx = fmaxf(mx, v);
            }
            mx = fmaxf(mx, __shfl_xor_sync(0xffffffffu, mx, 1));
            mx = fmaxf(mx, __shfl_xor_sync(0xffffffffu, mx, 2));
            float s = 0.0f;
#pragma unroll
            for (int i = 0; i < 16; ++i) {
                float e = __expf(vals[i] - mx);
                vals[i] = e;
                s += e;
            }
            s += __shfl_xor_sync(0xffffffffu, s, 1);
            s += __shfl_xor_sync(0xffffffffu, s, 2);
            float inv = 1.0f / s;
#pragma unroll
            for (int i = 0; i < 16; ++i) row[l4 * 16 + i] = vals[i] * inv;
        }
        __syncthreads();

        // ---- AV: outs[:, h*32 : h*32+32] = probs(64x64) @ v(64x32) ----
        {
            int t = wid;           // 8 tiles exactly
            int mt = t & 3;
            int nt = t >> 2;       // 0..1
            wmma::fragment<wmma::accumulator,16,16,8,float> acc;
            wmma::fill_fragment(acc, 0.0f);
#pragma unroll
            for (int kt = 0; kt < 8; ++kt) {
                wmma::fragment<wmma::matrix_a,16,16,8,wmma::precision::tf32,wmma::row_major> af;
                wmma::fragment<wmma::matrix_b,16,16,8,wmma::precision::tf32,wmma::row_major> bf;
                wmma::load_matrix_sync(af, als + mt * 16 * AL_LD + kt * 8, AL_LD);
                wmma::load_matrix_sync(bf, qkvs + kt * 8 * QK_LD + 64 + nt * 16, QK_LD);
                cvt_frag_a(af); cvt_frag_b_row(bf);
                wmma::mma_sync(acc, af, bf, acc);
            }
            wmma::store_matrix_sync(outs + mt * 16 * OUT_LD + h * 32 + nt * 16, acc, OUT_LD,
                                    wmma::mem_row_major);
        }
        __syncthreads();
    }

    // ---- proj: xs(64x192) = outs(64x192) @ proj_w^T ----
    for (int t = wid; t < 48; t += 8) {
        int mt = t & 3;
        int nt = t >> 2;          // 0..11
        wmma::fragment<wmma::accumulator,16,16,8,float> acc;
        wmma::fill_fragment(acc, 0.0f);
        const float* Bp = proj_w + (size_t)nt * 16 * CCH;
#pragma unroll 4
        for (int kt = 0; kt < 24; ++kt) {
            wmma::fragment<wmma::matrix_a,16,16,8,wmma::precision::tf32,wmma::row_major> af;
            wmma::fragment<wmma::matrix_b,16,16,8,wmma::precision::tf32,wmma::col_major> bf;
            wmma::load_matrix_sync(af, outs + mt * 16 * OUT_LD + kt * 8, OUT_LD);
            wmma::load_matrix_sync(bf, Bp + kt * 8, CCH);
            cvt_frag_a(af); cvt_frag_b_col(bf);
            wmma::mma_sync(acc, af, bf, acc);
        }
        wmma::store_matrix_sync(xs + mt * 16 * XS_LD + nt * 16, acc, XS_LD, wmma::mem_row_major);
    }
    __syncthreads();

    // ---- epilogue: add proj_b, scatter back to (B, H*W, C) layout ----
    {
        float* ob = out + (size_t)b * 65536 * CCH;
        for (int i = tid; i < 64 * 48; i += NTHREADS) {
            int r  = i / 48;
            int c4 = i % 48;
            float4 v  = *(float4*)(xs + r * XS_LD + c4 * 4);
            float4 pb = *(const float4*)(proj_b + c4 * 4);
            v.x += pb.x; v.y += pb.y; v.z += pb.z; v.w += pb.w;
            int iy = wh * 8 + (r >> 3);
            int ix = ww * 8 + (r & 7);
            *(float4*)(ob + (size_t)(iy * 256 + ix) * CCH + c4 * 4) = v;
        }
    }
}

extern "C" void kernel_launch(void* const* d_in, const int* in_sizes, int n_in,
                              void* d_out, int out_size)
{
    const float* x      = (const float*)d_in[0];
    const float* qkv_w  = (const float*)d_in[1];
    const float* qkv_b  = (const float*)d_in[2];
    const float* proj_w = (const float*)d_in[3];
    const float* proj_b = (const float*)d_in[4];
    const float* bias   = (const float*)d_in[5];
    float* out = (float*)d_out;

    cudaFuncSetAttribute(win_attn_kernel,
                         cudaFuncAttributeMaxDynamicSharedMemorySize, SMEM_BYTES);
    win_attn_kernel<<<NWIN, NTHREADS, SMEM_BYTES>>>(x, qkv_w, qkv_b, proj_w, proj_b, bias, out);
}

// round 2
// speedup vs baseline: 2.4374x; 2.4374x over previous
#include <cuda_runtime.h>
#include <mma.h>

using namespace nvcuda;

#define NWIN 4096       // 4 * 32 * 32 windows
#define CCH  192
#define NH   6
#define NTHREADS 384    // 12 warps

// smem strides (floats); stride mod 32 == 4 to stagger banks
#define XS_LD  196
#define QK_LD  580
#define AL_LD  68

#define SMEM_FLOATS (64*XS_LD + 64*QK_LD + 64*AL_LD)
#define SMEM_BYTES  (SMEM_FLOATS * 4)   // 216064 B

// fragment-ready packed weights: tiles of [8 rows(k)][16 cols(n)] contiguous
// qkv: 36 nt-tiles x 24 kt-tiles x 128 floats
__device__ float g_qkvw_packed[36 * 24 * 128];
// proj: 12 nt-tiles x 24 kt-tiles x 128 floats
__device__ float g_projw_packed[12 * 24 * 128];

__global__ void repack_kernel(const float* __restrict__ qkv_w,
                              const float* __restrict__ proj_w)
{
    int i = blockIdx.x * blockDim.x + threadIdx.x;
    const int NQ = 36 * 24 * 128;
    if (i < NQ) {
        int c  = i & 15;
        int r  = (i >> 4) & 7;
        int t  = i >> 7;          // nt*24 + kt
        int kt = t % 24;
        int nt = t / 24;
        // B[k][n] = W[n][k]  (for x @ W^T)
        g_qkvw_packed[i] = wmma::__float_to_tf32(qkv_w[(nt * 16 + c) * CCH + kt * 8 + r]);
    } else if (i < NQ + 12 * 24 * 128) {
        int j  = i - NQ;
        int c  = j & 15;
        int r  = (j >> 4) & 7;
        int t  = j >> 7;
        int kt = t % 24;
        int nt = t / 24;
        g_projw_packed[j] = wmma::__float_to_tf32(proj_w[(nt * 16 + c) * CCH + kt * 8 + r]);
    }
}

__device__ __forceinline__ void cvt_frag_a(
    wmma::fragment<wmma::matrix_a,16,16,8,wmma::precision::tf32,wmma::row_major>& f) {
#pragma unroll
    for (int i = 0; i < f.num_elements; i++) f.x[i] = wmma::__float_to_tf32(f.x[i]);
}

__global__ __launch_bounds__(NTHREADS, 1)
void win_attn_kernel(const float* __restrict__ x,
                     const float* __restrict__ qkv_b,
                     const float* __restrict__ proj_b,
                     const float* __restrict__ bias,
                     float* __restrict__ out)
{
    extern __shared__ float smem[];
    float* xs   = smem;                   // [64][XS_LD] x window; later AV outputs
    float* qkvs = xs + 64 * XS_LD;        // [64][QK_LD] full qkv (576 cols); later proj out
    float* als  = qkvs + 64 * QK_LD;      // [64][AL_LD] logits / probs

    const int tid = threadIdx.x;
    const int wid = tid >> 5;             // 0..11

    const int w   = blockIdx.x;
    const int b   = w >> 10;
    const int rem = w & 1023;
    const int wh  = rem >> 5;
    const int ww  = rem & 31;

    const float scale = 0.17677669529663687f; // 1/sqrt(32)

    // ---- load x window (64 x 192) into smem, tf32-rounded, coalesced float4 ----
    {
        const float* xb = x + (size_t)b * 65536 * CCH;
        for (int i = tid; i < 64 * 48; i += NTHREADS) {
            int r  = i / 48;
            int c4 = i % 48;
            int iy = wh * 8 + (r >> 3);
            int ix = ww * 8 + (r & 7);
            float4 v = *(const float4*)(xb + (size_t)(iy * 256 + ix) * CCH + c4 * 4);
            v.x = wmma::__float_to_tf32(v.x);
            v.y = wmma::__float_to_tf32(v.y);
            v.z = wmma::__float_to_tf32(v.z);
            v.w = wmma::__float_to_tf32(v.w);
            *(float4*)(xs + r * XS_LD + c4 * 4) = v;
        }
    }
    __syncthreads();

    // ---- GEMM1: qkvs(64x576) = xs(64x192) @ qkv_w^T, all heads at once.
    //      warp w owns nt columns {3w, 3w+1, 3w+2}; 4 mt accumulators each.
    {
        wmma::fragment<wmma::accumulator,16,16,8,float> acc[3][4];
#pragma unroll
        for (int i = 0; i < 3; ++i)
#pragma unroll
            for (int j = 0; j < 4; ++j) wmma::fill_fragment(acc[i][j], 0.0f);

        for (int kt = 0; kt < 24; ++kt) {
            wmma::fragment<wmma::matrix_a,16,16,8,wmma::precision::tf32,wmma::row_major> af[4];
#pragma unroll
            for (int j = 0; j < 4; ++j)
                wmma::load_matrix_sync(af[j], xs + j * 16 * XS_LD + kt * 8, XS_LD);
#pragma unroll
            for (int i = 0; i < 3; ++i) {
                wmma::fragment<wmma::matrix_b,16,16,8,wmma::precision::tf32,wmma::row_major> bf;
                wmma::load_matrix_sync(bf, g_qkvw_packed + ((3 * wid + i) * 24 + kt) * 128, 16);
#pragma unroll
                for (int j = 0; j < 4; ++j)
                    wmma::mma_sync(acc[i][j], af[j], bf, acc[i][j]);
            }
        }
#pragma unroll
        for (int i = 0; i < 3; ++i)
#pragma unroll
            for (int j = 0; j < 4; ++j)
                wmma::store_matrix_sync(qkvs + j * 16 * QK_LD + (3 * wid + i) * 16,
                                        acc[i][j], QK_LD, wmma::mem_row_major);
    }
    __syncthreads();

    // ---- bias add (+ fold softmax scale into q) + tf32 rounding, one pass ----
    for (int i = tid; i < 64 * 144; i += NTHREADS) {
        int r  = i / 144;
        int c4 = i % 144;
        float4 v  = *(float4*)(qkvs + r * QK_LD + c4 * 4);
        float4 bv = *(const float4*)(qkv_b + c4 * 4);
        v.x += bv.x; v.y += bv.y; v.z += bv.z; v.w += bv.w;
        if (c4 < 48) { v.x *= scale; v.y *= scale; v.z *= scale; v.w *= scale; }
        v.x = wmma::__float_to_tf32(v.x);
        v.y = wmma::__float_to_tf32(v.y);
        v.z = wmma::__float_to_tf32(v.z);
        v.w = wmma::__float_to_tf32(v.w);
        *(float4*)(qkvs + r * QK_LD + c4 * 4) = v;
    }
    __syncthreads();

    // ================= per-head attention =================
    for (int h = 0; h < NH; ++h) {
        const int qo = h * 32;          // q col offset
        const int ko = 192 + h * 32;    // k col offset
        const int vo = 384 + h * 32;    // v col offset

        // ---- logits: als = q_scaled @ k^T + bias (bias preloaded into acc) ----
        for (int t = wid; t < 16; t += 12) {
            int mt = t & 3;
            int nt = t >> 2;
            wmma::fragment<wmma::accumulator,16,16,8,float> acc;
            wmma::load_matrix_sync(acc, bias + (size_t)h * 4096 + mt * 16 * 64 + nt * 16,
                                   64, wmma::mem_row_major);
#pragma unroll
            for (int kt = 0; kt < 4; ++kt) {
                wmma::fragment<wmma::matrix_a,16,16,8,wmma::precision::tf32,wmma::row_major> af;
                wmma::fragment<wmma::matrix_b,16,16,8,wmma::precision::tf32,wmma::col_major> bf;
                wmma::load_matrix_sync(af, qkvs + mt * 16 * QK_LD + qo + kt * 8, QK_LD);
                wmma::load_matrix_sync(bf, qkvs + nt * 16 * QK_LD + ko + kt * 8, QK_LD);
                wmma::mma_sync(acc, af, bf, acc);
            }
            wmma::store_matrix_sync(als + mt * 16 * AL_LD + nt * 16, acc, AL_LD,
                                    wmma::mem_row_major);
        }
        __syncthreads();

        // ---- softmax over 64 rows x 64 cols (4 threads/row, threads 0..255) ----
        if (tid < 256) {
            int r  = tid >> 2;
            int l4 = tid & 3;
            float* row = als + r * AL_LD;
            float vals[16];
            float mx = -1e30f;
#pragma unroll
            for (int i = 0; i < 16; ++i) {
                float v = row[l4 * 16 + i];
                vals[i] = v;
                mx = fmaxf(mx, v);
            }
            mx = fmaxf(mx, __shfl_xor_sync(0xffffffffu, mx, 1));
            mx = fmaxf(mx, __shfl_xor_sync(0xffffffffu, mx, 2));
            float s = 0.0f;
#pragma unroll
            for (int i = 0; i < 16; ++i) {
                float e = __expf(vals[i] - mx);
                vals[i] = e;
                s += e;
            }
            s += __shfl_xor_sync(0xffffffffu, s, 1);
            s += __shfl_xor_sync(0xffffffffu, s, 2);
            float inv = 1.0f / s;
#pragma unroll
            for (int i = 0; i < 16; ++i)
                row[l4 * 16 + i] = wmma::__float_to_tf32(vals[i] * inv);
        }
        __syncthreads();

        // ---- AV: xs[:, h*32 : h*32+32] = probs(64x64) @ v(64x32) ----
        if (wid < 8) {
            int mt = wid & 3;
            int nt = wid >> 2;
            wmma::fragment<wmma::accumulator,16,16,8,float> acc;
            wmma::fill_fragment(acc, 0.0f);
#pragma unroll
            for (int kt = 0; kt < 8; ++kt) {
                wmma::fragment<wmma::matrix_a,16,16,8,wmma::precision::tf32,wmma::row_major> af;
                wmma::fragment<wmma::matrix_b,16,16,8,wmma::precision::tf32,wmma::row_major> bf;
                wmma::load_matrix_sync(af, als + mt * 16 * AL_LD + kt * 8, AL_LD);
                wmma::load_matrix_sync(bf, qkvs + kt * 8 * QK_LD + vo + nt * 16, QK_LD);
                wmma::mma_sync(acc, af, bf, acc);
            }
            wmma::store_matrix_sync(xs + mt * 16 * XS_LD + qo + nt * 16, acc, XS_LD,
                                    wmma::mem_row_major);
        }
        __syncthreads();
    }

    // ---- proj: qkvs[:, 0:192] = xs(64x192) @ proj_w^T ; warp w owns nt=w ----
    {
        wmma::fragment<wmma::accumulator,16,16,8,float> acc[4];
#pragma unroll
        for (int j = 0; j < 4; ++j) wmma::fill_fragment(acc[j], 0.0f);
        for (int kt = 0; kt < 24; ++kt) {
            wmma::fragment<wmma::matrix_b,16,16,8,wmma::precision::tf32,wmma::row_major> bf;
            wmma::load_matrix_sync(bf, g_projw_packed + (wid * 24 + kt) * 128, 16);
#pragma unroll
            for (int j = 0; j < 4; ++j) {
                wmma::fragment<wmma::matrix_a,16,16,8,wmma::precision::tf32,wmma::row_major> af;
                wmma::load_matrix_sync(af, xs + j * 16 * XS_LD + kt * 8, XS_LD);
                cvt_frag_a(af);
                wmma::mma_sync(acc[j], af, bf, acc[j]);
            }
        }
#pragma unroll
        for (int j = 0; j < 4; ++j)
            wmma::store_matrix_sync(qkvs + j * 16 * QK_LD + wid * 16, acc[j], QK_LD,
                                    wmma::mem_row_major);
    }
    __syncthreads();

    // ---- epilogue: add proj_b, scatter to (B, H*W, C) ----
    {
        float* ob = out + (size_t)b * 65536 * CCH;
        for (int i = tid; i < 64 * 48; i += NTHREADS) {
            int r  = i / 48;
            int c4 = i % 48;
            float4 v  = *(float4*)(qkvs + r * QK_LD + c4 * 4);
            float4 pb = *(const float4*)(proj_b + c4 * 4);
            v.x += pb.x; v.y += pb.y; v.z += pb.z; v.w += pb.w;
            int iy = wh * 8 + (r >> 3);
            int ix = ww * 8 + (r & 7);
            *(float4*)(ob + (size_t)(iy * 256 + ix) * CCH + c4 * 4) = v;
        }
    }
}

extern "C" void kernel_launch(void* const* d_in, const int* in_sizes, int n_in,
                              void* d_out, int out_size)
{
    const float* x      = (const float*)d_in[0];
    const float* qkv_w  = (const float*)d_in[1];
    const float* qkv_b  = (const float*)d_in[2];
    const float* proj_w = (const float*)d_in[3];
    const float* proj_b = (const float*)d_in[4];
    const float* bias   = (const float*)d_in[5];
    float* out = (float*)d_out;

    // repack weights into fragment-ready tf32 tiles (tiny, once per launch)
    repack_kernel<<<(147456 + 255) / 256, 256>>>(qkv_w, proj_w);

    cudaFuncSetAttribute(win_attn_kernel,
                         cudaFuncAttributeMaxDynamicSharedMemorySize, SMEM_BYTES);
    win_attn_kernel<<<NWIN, NTHREADS, SMEM_BYTES>>>(x, qkv_b, proj_b, bias, out);
}

// round 3
// speedup vs baseline: 2.6260x; 1.0774x over previous
#include <cuda_runtime.h>
#include <mma.h>

using namespace nvcuda;

#define NWIN 4096       // 4 * 32 * 32 windows
#define CCH  192
#define NH   6
#define NTHREADS 384    // 12 warps

#define XS_LD  196
#define QK_LD  580
#define AL_LD  68

// scratch region hosts x-window [64][196], then 3-head logits [192][68], then proj out
#define SCR_FLOATS (192 * AL_LD)          // 13056 >= 64*196 = 12544
#define SMEM_FLOATS (64 * QK_LD + SCR_FLOATS)
#define SMEM_BYTES  (SMEM_FLOATS * 4)     // 200704 B

// fragment-ready packed weights: tiles of [8 rows(k)][16 cols(n)] contiguous
__device__ float g_qkvw_packed[36 * 24 * 128];
__device__ float g_projw_packed[12 * 24 * 128];

__global__ void repack_kernel(const float* __restrict__ qkv_w,
                              const float* __restrict__ proj_w)
{
    int i = blockIdx.x * blockDim.x + threadIdx.x;
    const int NQ = 36 * 24 * 128;
    if (i < NQ) {
        int c  = i & 15;
        int r  = (i >> 4) & 7;
        int t  = i >> 7;          // nt*24 + kt
        int kt = t % 24;
        int nt = t / 24;
        g_qkvw_packed[i] = wmma::__float_to_tf32(qkv_w[(nt * 16 + c) * CCH + kt * 8 + r]);
    } else if (i < NQ + 12 * 24 * 128) {
        int j  = i - NQ;
        int c  = j & 15;
        int r  = (j >> 4) & 7;
        int t  = j >> 7;
        int kt = t % 24;
        int nt = t / 24;
        g_projw_packed[j] = wmma::__float_to_tf32(proj_w[(nt * 16 + c) * CCH + kt * 8 + r]);
    }
}

__global__ __launch_bounds__(NTHREADS, 1)
void win_attn_kernel(const float* __restrict__ x,
                     const float* __restrict__ qkv_b,
                     const float* __restrict__ proj_b,
                     const float* __restrict__ bias,
                     float* __restrict__ out)
{
    extern __shared__ float smem[];
    float* qkvs = smem;                   // [64][QK_LD] qkv (576 cols); q-region reused for AV out
    float* scr  = smem + 64 * QK_LD;      // x window / 3-head logits / proj out

    const int tid = threadIdx.x;
    const int wid = tid >> 5;             // 0..11

    const int w   = blockIdx.x;
    const int b   = w >> 10;
    const int rem = w & 1023;
    const int wh  = rem >> 5;
    const int ww  = rem & 31;

    const float scale = 0.17677669529663687f; // 1/sqrt(32)

    // ---- load x window (64 x 192) into scr, tf32-rounded, coalesced float4 ----
    {
        const float* xb = x + (size_t)b * 65536 * CCH;
        for (int i = tid; i < 64 * 48; i += NTHREADS) {
            int r  = i / 48;
            int c4 = i % 48;
            int iy = wh * 8 + (r >> 3);
            int ix = ww * 8 + (r & 7);
            float4 v = *(const float4*)(xb + (size_t)(iy * 256 + ix) * CCH + c4 * 4);
            v.x = wmma::__float_to_tf32(v.x);
            v.y = wmma::__float_to_tf32(v.y);
            v.z = wmma::__float_to_tf32(v.z);
            v.w = wmma::__float_to_tf32(v.w);
            *(float4*)(scr + r * XS_LD + c4 * 4) = v;
        }
    }
    __syncthreads();

    // ---- GEMM1: qkvs(64x576) = x(64x192) @ qkv_w^T, warp owns nt {3w,3w+1,3w+2} x 4 mt ----
    {
        wmma::fragment<wmma::accumulator,16,16,8,float> acc[3][4];
#pragma unroll
        for (int i = 0; i < 3; ++i)
#pragma unroll
            for (int j = 0; j < 4; ++j) wmma::fill_fragment(acc[i][j], 0.0f);

        for (int kt = 0; kt < 24; ++kt) {
            wmma::fragment<wmma::matrix_a,16,16,8,wmma::precision::tf32,wmma::row_major> af[4];
#pragma unroll
            for (int j = 0; j < 4; ++j)
                wmma::load_matrix_sync(af[j], scr + j * 16 * XS_LD + kt * 8, XS_LD);
#pragma unroll
            for (int i = 0; i < 3; ++i) {
                wmma::fragment<wmma::matrix_b,16,16,8,wmma::precision::tf32,wmma::row_major> bf;
                wmma::load_matrix_sync(bf, g_qkvw_packed + ((3 * wid + i) * 24 + kt) * 128, 16);
#pragma unroll
                for (int j = 0; j < 4; ++j)
                    wmma::mma_sync(acc[i][j], af[j], bf, acc[i][j]);
            }
        }
#pragma unroll
        for (int i = 0; i < 3; ++i)
#pragma unroll
            for (int j = 0; j < 4; ++j)
                wmma::store_matrix_sync(qkvs + j * 16 * QK_LD + (3 * wid + i) * 16,
                                        acc[i][j], QK_LD, wmma::mem_row_major);
    }
    __syncthreads();

    // ---- bias add (+ fold softmax scale into q) + tf32 rounding, one pass ----
    for (int i = tid; i < 64 * 144; i += NTHREADS) {
        int r  = i / 144;
        int c4 = i % 144;
        float4 v  = *(float4*)(qkvs + r * QK_LD + c4 * 4);
        float4 bv = *(const float4*)(qkv_b + c4 * 4);
        v.x += bv.x; v.y += bv.y; v.z += bv.z; v.w += bv.w;
        if (c4 < 48) { v.x *= scale; v.y *= scale; v.z *= scale; v.w *= scale; }
        v.x = wmma::__float_to_tf32(v.x);
        v.y = wmma::__float_to_tf32(v.y);
        v.z = wmma::__float_to_tf32(v.z);
        v.w = wmma::__float_to_tf32(v.w);
        *(float4*)(qkvs + r * QK_LD + c4 * 4) = v;
    }
    __syncthreads();

    // ================= attention, 3 heads per group, 2 groups =================
    const int hl = wid >> 2;              // head_local 0..2
    const int mt = wid & 3;               // row-stripe 0..3

    for (int g = 0; g < 2; ++g) {
        const int h  = 3 * g + hl;
        const int qo = h * 32;
        const int ko = 192 + h * 32;
        const int vo = 384 + h * 32;
        float* alsh = scr + (hl * 64 + mt * 16) * AL_LD;

        // ---- logits: row-stripe mt of head h across all 4 nt; bias preloaded ----
        {
            wmma::fragment<wmma::accumulator,16,16,8,float> acc[4];
#pragma unroll
            for (int nt = 0; nt < 4; ++nt)
                wmma::load_matrix_sync(acc[nt],
                    bias + (size_t)h * 4096 + mt * 16 * 64 + nt * 16, 64,
                    wmma::mem_row_major);
#pragma unroll
            for (int kt = 0; kt < 4; ++kt) {
                wmma::fragment<wmma::matrix_a,16,16,8,wmma::precision::tf32,wmma::row_major> af;
                wmma::load_matrix_sync(af, qkvs + mt * 16 * QK_LD + qo + kt * 8, QK_LD);
#pragma unroll
                for (int nt = 0; nt < 4; ++nt) {
                    wmma::fragment<wmma::matrix_b,16,16,8,wmma::precision::tf32,wmma::col_major> bf;
                    wmma::load_matrix_sync(bf, qkvs + nt * 16 * QK_LD + ko + kt * 8, QK_LD);
                    wmma::mma_sync(acc[nt], af, bf, acc[nt]);
                }
            }
#pragma unroll
            for (int nt = 0; nt < 4; ++nt)
                wmma::store_matrix_sync(alsh + nt * 16, acc[nt], AL_LD, wmma::mem_row_major);
        }
        __syncthreads();

        // ---- softmax: 192 rows x 64 cols, 2 threads per row ----
        {
            int r    = tid >> 1;          // 0..191
            int half = tid & 1;
            float* row = scr + r * AL_LD + half * 32;
            float vals[32];
            float mx = -1e30f;
#pragma unroll
            for (int i = 0; i < 8; ++i) {
                float4 v = *(float4*)(row + i * 4);
                vals[i*4+0] = v.x; vals[i*4+1] = v.y; vals[i*4+2] = v.z; vals[i*4+3] = v.w;
                mx = fmaxf(mx, fmaxf(fmaxf(v.x, v.y), fmaxf(v.z, v.w)));
            }
            mx = fmaxf(mx, __shfl_xor_sync(0xffffffffu, mx, 1));
            float s = 0.0f;
#pragma unroll
            for (int i = 0; i < 32; ++i) {
                float e = __expf(vals[i] - mx);
                vals[i] = e;
                s += e;
            }
            s += __shfl_xor_sync(0xffffffffu, s, 1);
            float inv = 1.0f / s;
#pragma unroll
            for (int i = 0; i < 8; ++i) {
                float4 v;
                v.x = wmma::__float_to_tf32(vals[i*4+0] * inv);
                v.y = wmma::__float_to_tf32(vals[i*4+1] * inv);
                v.z = wmma::__float_to_tf32(vals[i*4+2] * inv);
                v.w = wmma::__float_to_tf32(vals[i*4+3] * inv);
                *(float4*)(row + i * 4) = v;
            }
        }
        __syncthreads();

        // ---- AV: out-stripe mt of head h -> q-region cols [qo, qo+32) ----
        {
            wmma::fragment<wmma::accumulator,16,16,8,float> acc[2];
#pragma unroll
            for (int nt = 0; nt < 2; ++nt) wmma::fill_fragment(acc[nt], 0.0f);
#pragma unroll
            for (int kt = 0; kt < 8; ++kt) {
                wmma::fragment<wmma::matrix_a,16,16,8,wmma::precision::tf32,wmma::row_major> af;
                wmma::load_matrix_sync(af, alsh + kt * 8, AL_LD);
#pragma unroll
                for (int nt = 0; nt < 2; ++nt) {
                    wmma::fragment<wmma::matrix_b,16,16,8,wmma::precision::tf32,wmma::row_major> bf;
                    wmma::load_matrix_sync(bf, qkvs + kt * 8 * QK_LD + vo + nt * 16, QK_LD);
                    wmma::mma_sync(acc[nt], af, bf, acc[nt]);
                }
            }
#pragma unroll
            for (int nt = 0; nt < 2; ++nt)
                wmma::store_matrix_sync(qkvs + mt * 16 * QK_LD + qo + nt * 16, acc[nt],
                                        QK_LD, wmma::mem_row_major);
        }
        __syncthreads();
    }

    // ---- round AV outputs (qkvs cols 0..191) to tf32 for proj ----
    for (int i = tid; i < 64 * 48; i += NTHREADS) {
        int r  = i / 48;
        int c4 = i % 48;
        float4 v = *(float4*)(qkvs + r * QK_LD + c4 * 4);
        v.x = wmma::__float_to_tf32(v.x);
        v.y = wmma::__float_to_tf32(v.y);
        v.z = wmma::__float_to_tf32(v.z);
        v.w = wmma::__float_to_tf32(v.w);
        *(float4*)(qkvs + r * QK_LD + c4 * 4) = v;
    }
    __syncthreads();

    // ---- proj: scr(64x192) = attn_out(64x192) @ proj_w^T ; warp w owns nt=w ----
    {
        wmma::fragment<wmma::accumulator,16,16,8,float> acc[4];
#pragma unroll
        for (int j = 0; j < 4; ++j) wmma::fill_fragment(acc[j], 0.0f);
        for (int kt = 0; kt < 24; ++kt) {
            wmma::fragment<wmma::matrix_b,16,16,8,wmma::precision::tf32,wmma::row_major> bf;
            wmma::load_matrix_sync(bf, g_projw_packed + (wid * 24 + kt) * 128, 16);
#pragma unroll
            for (int j = 0; j < 4; ++j) {
                wmma::fragment<wmma::matrix_a,16,16,8,wmma::precision::tf32,wmma::row_major> af;
                wmma::load_matrix_sync(af, qkvs + j * 16 * QK_LD + kt * 8, QK_LD);
                wmma::mma_sync(acc[j], af, bf, acc[j]);
            }
        }
#pragma unroll
        for (int j = 0; j < 4; ++j)
            wmma::store_matrix_sync(scr + j * 16 * XS_LD + wid * 16, acc[j], XS_LD,
                                    wmma::mem_row_major);
    }
    __syncthreads();

    // ---- epilogue: add proj_b, scatter to (B, H*W, C) ----
    {
        float* ob = out + (size_t)b * 65536 * CCH;
        for (int i = tid; i < 64 * 48; i += NTHREADS) {
            int r  = i / 48;
            int c4 = i % 48;
            float4 v  = *(float4*)(scr + r * XS_LD + c4 * 4);
            float4 pb = *(const float4*)(proj_b + c4 * 4);
            v.x += pb.x; v.y += pb.y; v.z += pb.z; v.w += pb.w;
            int iy = wh * 8 + (r >> 3);
            int ix = ww * 8 + (r & 7);
            *(float4*)(ob + (size_t)(iy * 256 + ix) * CCH + c4 * 4) = v;
        }
    }
}

extern "C" void kernel_launch(void* const* d_in, const int* in_sizes, int n_in,
                              void* d_out, int out_size)
{
    const float* x      = (const float*)d_in[0];
    const float* qkv_w  = (const float*)d_in[1];
    const float* qkv_b  = (const float*)d_in[2];
    const float* proj_w = (const float*)d_in[3];
    const float* proj_b = (const float*)d_in[4];
    const float* bias   = (const float*)d_in[5];
    float* out = (float*)d_out;

    repack_kernel<<<(147456 + 255) / 256, 256>>>(qkv_w, proj_w);

    cudaFuncSetAttribute(win_attn_kernel,
                         cudaFuncAttributeMaxDynamicSharedMemorySize, SMEM_BYTES);
    win_attn_kernel<<<NWIN, NTHREADS, SMEM_BYTES>>>(x, qkv_b, proj_b, bias, out);
}